// round 14
// baseline (speedup 1.0000x reference)
#include <cuda_runtime.h>
#include <math.h>

#define NN 50000
#define EE 400000
#define E2 (EE + 50000)
#define XI_LD 264

// ---------------- scratch ----------------
__device__ float g_xi[NN * XI_LD + 64];
__device__ float g_xlr[NN * 512 + 64];   // xl|xr; reused as P12 for classifier
__device__ float g_la[NN * 64 + 64];
__device__ float g_xout[NN * 128];
__device__ float g_xin[NN * 128];
__device__ float g_lsum[NN * 64];
__device__ float g_degs[NN];
__device__ float g_degd[NN];
__device__ float g_h1[NN * 128 + 64];
__device__ float g_h2[NN * 128 + 64];
__device__ float g_logit[E2 * 2];
__device__ int   g_csr_off[NN + 1];
__device__ int   g_csr_pos[NN];
__device__ int   g_csr_edge[E2];
__device__ int   g_bsum[64];

// ---------------- helpers ----------------
__device__ __forceinline__ float lrelu02(float x) { return x > 0.f ? x : 0.2f * x; }

__device__ __forceinline__ float warp_sum(float v) {
#pragma unroll
    for (int o = 16; o; o >>= 1) v += __shfl_xor_sync(0xffffffffu, v, o);
    return v;
}
__device__ __forceinline__ int warp_sum_i(int v) {
#pragma unroll
    for (int o = 16; o; o >>= 1) v += __shfl_xor_sync(0xffffffffu, v, o);
    return v;
}

__device__ __forceinline__ void redv2(float* p, float a, float b) {
    asm volatile("red.global.add.v2.f32 [%0], {%1, %2};" :: "l"(p), "f"(a), "f"(b) : "memory");
}
__device__ __forceinline__ void redv4(float* p, float a, float b, float c, float d) {
    asm volatile("red.global.add.v4.f32 [%0], {%1, %2, %3, %4};"
                 :: "l"(p), "f"(a), "f"(b), "f"(c), "f"(d) : "memory");
}

__device__ __forceinline__ unsigned f2tf(float x) {
    unsigned u;
    asm("cvt.rna.tf32.f32 %0, %1;" : "=r"(u) : "f"(x));
    return u;
}

__device__ __forceinline__ void mma_tf32(float c[4], const unsigned a[4], const unsigned b[2]) {
    asm volatile(
        "mma.sync.aligned.m16n8k8.row.col.f32.tf32.tf32.f32 "
        "{%0,%1,%2,%3},{%4,%5,%6,%7},{%8,%9},{%0,%1,%2,%3};"
        : "+f"(c[0]), "+f"(c[1]), "+f"(c[2]), "+f"(c[3])
        : "r"(a[0]), "r"(a[1]), "r"(a[2]), "r"(a[3]), "r"(b[0]), "r"(b[1]));
}

// ======== wide TF32 GEMM: BM=128 BN=128 BK=32, 512 threads ========
// EPI: 0 = store C (+relu if ACT), 1 = emb scatter + ea sums
// B2: if non-null, B is column-concat [B | B2], each with row stride N/2.
template <int ACT, int EPI>
__global__ __launch_bounds__(512, 1)
void gemm128(const float* __restrict__ A, int lda, int K,
             const float* __restrict__ B, const float* __restrict__ B2,
             const float* __restrict__ bias,
             float* __restrict__ C, int M, int N,
             const int* __restrict__ gsrc, const int* __restrict__ gdst,
             const float* __restrict__ ea) {
    __shared__ unsigned As[128][36];
    __shared__ unsigned Bs[32][136];
    int tid = threadIdx.x;
    int warp = tid >> 5, lane = tid & 31;
    int wm = warp & 3, wn = warp >> 2;
    int rowBase = blockIdx.y * 128;
    int colBase = blockIdx.x * 128;
    int q = lane >> 2, r4 = lane & 3;

    float acc[2][4][4];
#pragma unroll
    for (int mt = 0; mt < 2; mt++)
#pragma unroll
        for (int nt = 0; nt < 4; nt++)
#pragma unroll
            for (int j = 0; j < 4; j++) acc[mt][nt][j] = 0.f;

    float4 pa[2], pb[2];
    auto loadA = [&](int k0) {
#pragma unroll
        for (int i = 0; i < 2; i++) {
            int idx = tid + i * 512;
            int row = idx >> 3, kk = (idx & 7) * 4;
            int gk = k0 + kk;
            float4 v = make_float4(0.f, 0.f, 0.f, 0.f);
            int gr = rowBase + row;
            if (gr < M && gk < lda) v = *(const float4*)(A + (size_t)gr * lda + gk);
            pa[i] = v;
        }
    };
    auto loadB = [&](int k0) {
#pragma unroll
        for (int i = 0; i < 2; i++) {
            int idx = tid + i * 512;
            int kk = idx >> 5, cc = (idx & 31) * 4;
            int gk = k0 + kk;
            float4 v = make_float4(0.f, 0.f, 0.f, 0.f);
            if (gk < K) {
                int gc = colBase + cc;
                if (B2) {
                    int N1 = N >> 1;
                    v = (gc < N1) ? *(const float4*)(B + (size_t)gk * N1 + gc)
                                  : *(const float4*)(B2 + (size_t)gk * N1 + gc - N1);
                } else {
                    v = *(const float4*)(B + (size_t)gk * N + gc);
                }
            }
            pb[i] = v;
        }
    };
    auto stsAB = [&]() {
#pragma unroll
        for (int i = 0; i < 2; i++) {
            int idx = tid + i * 512;
            int row = idx >> 3, kk = (idx & 7) * 4;
            uint4 t;
            t.x = f2tf(pa[i].x); t.y = f2tf(pa[i].y); t.z = f2tf(pa[i].z); t.w = f2tf(pa[i].w);
            *(uint4*)&As[row][kk] = t;
            int kb = idx >> 5, cc = (idx & 31) * 4;
            uint4 u;
            u.x = f2tf(pb[i].x); u.y = f2tf(pb[i].y); u.z = f2tf(pb[i].z); u.w = f2tf(pb[i].w);
            *(uint4*)&Bs[kb][cc] = u;
        }
    };

    loadA(0); loadB(0);
    for (int k0 = 0; k0 < K; k0 += 32) {
        stsAB();
        __syncthreads();
        if (k0 + 32 < K) { loadA(k0 + 32); loadB(k0 + 32); }
#pragma unroll
        for (int ks = 0; ks < 4; ks++) {
            int kb = ks * 8;
            unsigned af[2][4], bf[4][2];
#pragma unroll
            for (int mt = 0; mt < 2; mt++) {
                int r0 = wm * 32 + mt * 16 + q;
                af[mt][0] = As[r0][kb + r4];
                af[mt][1] = As[r0 + 8][kb + r4];
                af[mt][2] = As[r0][kb + r4 + 4];
                af[mt][3] = As[r0 + 8][kb + r4 + 4];
            }
#pragma unroll
            for (int nt = 0; nt < 4; nt++) {
                int c0 = wn * 32 + nt * 8 + q;
                bf[nt][0] = Bs[kb + r4][c0];
                bf[nt][1] = Bs[kb + r4 + 4][c0];
            }
#pragma unroll
            for (int mt = 0; mt < 2; mt++)
#pragma unroll
                for (int nt = 0; nt < 4; nt++) mma_tf32(acc[mt][nt], af[mt], bf[nt]);
        }
        __syncthreads();
    }

    if (EPI == 0) {
#pragma unroll
        for (int mt = 0; mt < 2; mt++) {
            int gr0 = rowBase + wm * 32 + mt * 16 + q;
            int gr1 = gr0 + 8;
#pragma unroll
            for (int nt = 0; nt < 4; nt++) {
                int gc = colBase + wn * 32 + nt * 8 + r4 * 2;
                float2 bv = make_float2(0.f, 0.f);
                if (bias) bv = *(const float2*)(bias + gc);
                float o0 = acc[mt][nt][0] + bv.x, o1 = acc[mt][nt][1] + bv.y;
                float o2 = acc[mt][nt][2] + bv.x, o3 = acc[mt][nt][3] + bv.y;
                if (ACT == 1) {
                    o0 = fmaxf(o0, 0.f); o1 = fmaxf(o1, 0.f);
                    o2 = fmaxf(o2, 0.f); o3 = fmaxf(o3, 0.f);
                }
                if (gr0 < M) *(float2*)(C + (size_t)gr0 * N + gc) = make_float2(o0, o1);
                if (gr1 < M) *(float2*)(C + (size_t)gr1 * N + gc) = make_float2(o2, o3);
            }
        }
    } else {
        // emb scatter: relu(acc+bias) -> xout[src], xin[dst]
#pragma unroll
        for (int mt = 0; mt < 2; mt++) {
            int gr0 = rowBase + wm * 32 + mt * 16 + q;
            int gr1 = gr0 + 8;
            int s0 = __ldg(gsrc + gr0), d0 = __ldg(gdst + gr0);
            int s1 = __ldg(gsrc + gr1), d1 = __ldg(gdst + gr1);
#pragma unroll
            for (int nt = 0; nt < 4; nt++) {
                int gc = wn * 32 + nt * 8 + r4 * 2;
                float2 bv = *(const float2*)(bias + gc);
                float v0 = fmaxf(acc[mt][nt][0] + bv.x, 0.f);
                float v1 = fmaxf(acc[mt][nt][1] + bv.y, 0.f);
                float v2 = fmaxf(acc[mt][nt][2] + bv.x, 0.f);
                float v3 = fmaxf(acc[mt][nt][3] + bv.y, 0.f);
                redv2(&g_xout[(size_t)s0 * 128 + gc], v0, v1);
                redv2(&g_xin[(size_t)d0 * 128 + gc], v0, v1);
                redv2(&g_xout[(size_t)s1 * 128 + gc], v2, v3);
                redv2(&g_xin[(size_t)d1 * 128 + gc], v2, v3);
            }
        }
        int row = tid >> 2, part = tid & 3;
        int e = rowBase + row;
        int s = __ldg(gsrc + e), d = __ldg(gdst + e);
        const float4* pea = (const float4*)(ea + (size_t)e * 64) + part * 4;
#pragma unroll
        for (int j = 0; j < 4; j++) {
            float4 v = pea[j];
            redv4(&g_lsum[(size_t)d * 64 + part * 16 + j * 4], v.x, v.y, v.z, v.w);
        }
        if (part == 0) { atomicAdd(&g_degs[s], 1.f); atomicAdd(&g_degd[d], 1.f); }
    }
}

// ======== CSR build ========
__global__ void csr_blocksum() {
    int v = blockIdx.x * 1024 + threadIdx.x;
    int c = (v < NN) ? (int)(g_degd[v] + 0.5f) + 1 : 0;
    __shared__ int ws[32];
    int wsum = warp_sum_i(c);
    if ((threadIdx.x & 31) == 0) ws[threadIdx.x >> 5] = wsum;
    __syncthreads();
    if (threadIdx.x < 32) {
        int t = ws[threadIdx.x];
        t = warp_sum_i(t);
        if (threadIdx.x == 0) g_bsum[blockIdx.x] = t;
    }
}
__global__ void csr_scanblocks(int nb) {
    if (threadIdx.x == 0) {
        int run = 0;
        for (int b = 0; b < nb; b++) { int t = g_bsum[b]; g_bsum[b] = run; run += t; }
    }
}
__global__ void csr_finalize() {
    __shared__ int sm[1024];
    int tid = threadIdx.x;
    int v = blockIdx.x * 1024 + tid;
    int c = (v < NN) ? (int)(g_degd[v] + 0.5f) + 1 : 0;
    sm[tid] = c;
    __syncthreads();
    for (int o = 1; o < 1024; o <<= 1) {
        int t = (tid >= o) ? sm[tid - o] : 0;
        __syncthreads();
        sm[tid] += t;
        __syncthreads();
    }
    int incl = sm[tid];
    int base = g_bsum[blockIdx.x];
    if (v < NN) {
        int off = base + incl - c;
        g_csr_off[v] = off;
        g_csr_pos[v] = off;
        if (v == NN - 1) g_csr_off[NN] = base + incl;
    }
}
__global__ void csr_scatter(const int* __restrict__ dst) {
    int i = blockIdx.x * blockDim.x + threadIdx.x;
    if (i < EE) {
        int d = dst[i];
        int pos = atomicAdd(&g_csr_pos[d], 1);
        g_csr_edge[pos] = i;
    } else if (i < E2) {
        int v = i - EE;
        g_csr_edge[g_csr_off[v + 1] - 1] = i;   // self-loop last in segment
    }
}

// ======== ew GEMM + GATv2 logit (CSR edge order, logits only) ========
template <int H>
__global__ void k_gat_edge(const float* __restrict__ ea, const float* __restrict__ la,
                           const float* __restrict__ we, const float* __restrict__ att,
                           const float* __restrict__ xlr,
                           const int* __restrict__ src, const int* __restrict__ dst) {
    const int W = 2 * H * 128;
    const int XOFF = H * 128;
    const int NB = H * 128;
    __shared__ unsigned As[128][68];
    __shared__ unsigned Bs[32][72];
    __shared__ float sp[128][2];
    __shared__ float lg[H][128];
    int tid = threadIdx.x;
    int warp = tid >> 5, lane = tid & 31;
    int wm = warp & 3, wn = warp >> 2;
    int q = lane >> 2, r4 = lane & 3;
    int e0 = blockIdx.x * 128;

    for (int i = tid; i < H * 128; i += 256) lg[i >> 7][i & 127] = 0.f;

#pragma unroll
    for (int i = 0; i < 8; i++) {
        int idx = tid + i * 256;
        int row = idx >> 4, gc = (idx & 15) * 4;
        int p = e0 + row;
        float4 v = make_float4(0.f, 0.f, 0.f, 0.f);
        if (p < E2) {
            int e = __ldg(g_csr_edge + p);
            if (e < EE) v = *(const float4*)(ea + (size_t)e * 64 + gc);
            else        v = *(const float4*)(la + (size_t)(e - EE) * 64 + gc);
        }
        uint4 t;
        t.x = f2tf(v.x); t.y = f2tf(v.y); t.z = f2tf(v.z); t.w = f2tf(v.w);
        *(uint4*)&As[row][gc] = t;
    }
    int ss[2][2], dd[2][2];
    bool vld[2][2];
#pragma unroll
    for (int mt = 0; mt < 2; mt++)
#pragma unroll
        for (int hf = 0; hf < 2; hf++) {
            int p = e0 + wm * 32 + mt * 16 + hf * 8 + q;
            bool v = p < E2;
            vld[mt][hf] = v;
            if (!v) { ss[mt][hf] = 0; dd[mt][hf] = 0; }
            else {
                int e = __ldg(g_csr_edge + p);
                if (e < EE) { ss[mt][hf] = __ldg(src + e); dd[mt][hf] = __ldg(dst + e); }
                else { ss[mt][hf] = e - EE; dd[mt][hf] = e - EE; }
            }
        }
    __syncthreads();

    for (int strip = 0; strip < 2 * H; strip++) {
        float acc[2][4][4];
#pragma unroll
        for (int mt = 0; mt < 2; mt++)
#pragma unroll
            for (int nt = 0; nt < 4; nt++)
#pragma unroll
                for (int j = 0; j < 4; j++) acc[mt][nt][j] = 0.f;

        for (int kt = 0; kt < 2; kt++) {
            __syncthreads();
#pragma unroll
            for (int i = 0; i < 2; i++) {
                int idx = tid + i * 256;
                int kk = idx >> 4, cc = (idx & 15) * 4;
                float4 v = *(const float4*)(we + (size_t)(kt * 32 + kk) * NB + strip * 64 + cc);
                uint4 t;
                t.x = f2tf(v.x); t.y = f2tf(v.y); t.z = f2tf(v.z); t.w = f2tf(v.w);
                *(uint4*)&Bs[kk][cc] = t;
            }
            __syncthreads();
#pragma unroll
            for (int ks = 0; ks < 4; ks++) {
                int kb = ks * 8;
                unsigned af[2][4], bf[4][2];
#pragma unroll
                for (int mt = 0; mt < 2; mt++) {
                    int r0 = wm * 32 + mt * 16 + q;
                    int ka = kt * 32 + kb;
                    af[mt][0] = As[r0][ka + r4];
                    af[mt][1] = As[r0 + 8][ka + r4];
                    af[mt][2] = As[r0][ka + r4 + 4];
                    af[mt][3] = As[r0 + 8][ka + r4 + 4];
                }
#pragma unroll
                for (int nt = 0; nt < 4; nt++) {
                    int c0 = wn * 32 + nt * 8 + q;
                    bf[nt][0] = Bs[kb + r4][c0];
                    bf[nt][1] = Bs[kb + r4 + 4][c0];
                }
#pragma unroll
                for (int mt = 0; mt < 2; mt++)
#pragma unroll
                    for (int nt = 0; nt < 4; nt++) mma_tf32(acc[mt][nt], af[mt], bf[nt]);
            }
        }

        int h = strip >> 1;
        float prow[2][2] = {{0.f, 0.f}, {0.f, 0.f}};
#pragma unroll
        for (int mt = 0; mt < 2; mt++) {
#pragma unroll
            for (int nt = 0; nt < 4; nt++) {
                int gc = strip * 64 + wn * 32 + nt * 8 + r4 * 2;
                int ch = gc & 127;
                float2 at = *(const float2*)(att + h * 128 + ch);
                if (vld[mt][0]) {
                    float2 xv = *(const float2*)(xlr + (size_t)ss[mt][0] * W + h * 128 + ch);
                    float2 rv = *(const float2*)(xlr + (size_t)dd[mt][0] * W + XOFF + h * 128 + ch);
                    prow[mt][0] += lrelu02(acc[mt][nt][0] + xv.x + rv.x) * at.x +
                                   lrelu02(acc[mt][nt][1] + xv.y + rv.y) * at.y;
                }
                if (vld[mt][1]) {
                    float2 xv = *(const float2*)(xlr + (size_t)ss[mt][1] * W + h * 128 + ch);
                    float2 rv = *(const float2*)(xlr + (size_t)dd[mt][1] * W + XOFF + h * 128 + ch);
                    prow[mt][1] += lrelu02(acc[mt][nt][2] + xv.x + rv.x) * at.x +
                                   lrelu02(acc[mt][nt][3] + xv.y + rv.y) * at.y;
                }
            }
        }
#pragma unroll
        for (int mt = 0; mt < 2; mt++)
#pragma unroll
            for (int hf = 0; hf < 2; hf++) {
                float p = prow[mt][hf];
                p += __shfl_xor_sync(0xffffffffu, p, 1);
                p += __shfl_xor_sync(0xffffffffu, p, 2);
                if (r4 == 0) sp[wm * 32 + mt * 16 + hf * 8 + q][wn] = p;
            }
        __syncthreads();
        if (tid < 128) lg[h][tid] += sp[tid][0] + sp[tid][1];
    }
    __syncthreads();
    if (tid < 128) {
        int p = e0 + tid;
        if (p < E2) {
#pragma unroll
            for (int h = 0; h < H; h++) g_logit[(size_t)p * H + h] = lg[h][tid];
        }
    }
}

// ======== warp-per-node: softmax-aggregate + heads mean + LN + ELU ========
template <int H>
__global__ void k_gat_gather(const float* __restrict__ xlr, const int* __restrict__ src,
                             const float* __restrict__ bias, const float* __restrict__ gam,
                             const float* __restrict__ bet, float* __restrict__ out) {
    const int W = 2 * H * 128;
    int v = (blockIdx.x * blockDim.x + threadIdx.x) >> 5;
    int lane = threadIdx.x & 31;
    if (v >= NN) return;
    int beg = g_csr_off[v], end = g_csr_off[v + 1];
    float acc[H][4];
    float den[H];
#pragma unroll
    for (int h = 0; h < H; h++) {
        den[h] = 0.f;
#pragma unroll
        for (int j = 0; j < 4; j++) acc[h][j] = 0.f;
    }
    for (int p = beg; p < end; p++) {
        int e = __ldg(g_csr_edge + p);
        int s = (e < EE) ? __ldg(src + e) : v;
#pragma unroll
        for (int h = 0; h < H; h++) {
            float a = expf(__ldg(g_logit + (size_t)p * H + h));
            den[h] += a;
            float4 x = ((const float4*)(xlr + (size_t)s * W + h * 128))[lane];
            acc[h][0] += a * x.x; acc[h][1] += a * x.y;
            acc[h][2] += a * x.z; acc[h][3] += a * x.w;
        }
    }
    float vals[4];
    int c0 = lane * 4;
    if (H == 2) {
        float i0 = 1.f / fmaxf(den[0], 1e-16f);
        float i1 = 1.f / fmaxf(den[1], 1e-16f);
#pragma unroll
        for (int j = 0; j < 4; j++)
            vals[j] = 0.5f * (acc[0][j] * i0 + acc[H - 1][j] * i1) + bias[c0 + j];
    } else {
        float i0 = 1.f / fmaxf(den[0], 1e-16f);
#pragma unroll
        for (int j = 0; j < 4; j++) vals[j] = acc[0][j] * i0 + bias[c0 + j];
    }
    float mu = warp_sum(vals[0] + vals[1] + vals[2] + vals[3]) * (1.f / 128.f);
    float sq = 0.f;
#pragma unroll
    for (int j = 0; j < 4; j++) { float dlt = vals[j] - mu; sq += dlt * dlt; }
    float var = warp_sum(sq) * (1.f / 128.f);
    float rstd = rsqrtf(var + 1e-5f);
#pragma unroll
    for (int j = 0; j < 4; j++) {
        int c = c0 + j;
        float y = (vals[j] - mu) * rstd * gam[c] + bet[c];
        out[(size_t)v * 128 + c] = y > 0.f ? y : (expf(y) - 1.f);
    }
}

// ======== classifier edge kernel: ea@c1w_e + P1[s]+P2[d] -> relu -> c2 -> c3 ========
__global__ __launch_bounds__(512, 1)
void k_cls_edge(const float* __restrict__ c1w, const float* __restrict__ c1b,
                const float* __restrict__ c2w, const float* __restrict__ c2b,
                const float* __restrict__ w3, const float* __restrict__ b3,
                const int* __restrict__ gsrc, const int* __restrict__ gdst,
                const float* __restrict__ p12, const float* __restrict__ ea,
                float* __restrict__ out) {
    __shared__ unsigned As[128][36];
    __shared__ unsigned Bs[32][136];
    __shared__ float sp[128][4];
    int tid = threadIdx.x;
    int warp = tid >> 5, lane = tid & 31;
    int wm = warp & 3, wn = warp >> 2;
    int rowBase = blockIdx.x * 128;
    int q = lane >> 2, r4 = lane & 3;

    // ---- stage 1: ea(128x64) @ c1w[256:320] (64x128) ----
    float acc[2][4][4];
#pragma unroll
    for (int mt = 0; mt < 2; mt++)
#pragma unroll
        for (int nt = 0; nt < 4; nt++)
#pragma unroll
            for (int j = 0; j < 4; j++) acc[mt][nt][j] = 0.f;

    for (int k0 = 0; k0 < 64; k0 += 32) {
#pragma unroll
        for (int i = 0; i < 2; i++) {
            int idx = tid + i * 512;
            int row = idx >> 3, kk = (idx & 7) * 4;
            float4 v = *(const float4*)(ea + (size_t)(rowBase + row) * 64 + k0 + kk);
            uint4 t;
            t.x = f2tf(v.x); t.y = f2tf(v.y); t.z = f2tf(v.z); t.w = f2tf(v.w);
            *(uint4*)&As[row][kk] = t;
        }
#pragma unroll
        for (int i = 0; i < 2; i++) {
            int idx = tid + i * 512;
            int kk = idx >> 5, cc = (idx & 31) * 4;
            float4 v = *(const float4*)(c1w + (size_t)(256 + k0 + kk) * 128 + cc);
            uint4 t;
            t.x = f2tf(v.x); t.y = f2tf(v.y); t.z = f2tf(v.z); t.w = f2tf(v.w);
            *(uint4*)&Bs[kk][cc] = t;
        }
        __syncthreads();
#pragma unroll
        for (int ks = 0; ks < 4; ks++) {
            int kb = ks * 8;
            unsigned af[2][4], bf[4][2];
#pragma unroll
            for (int mt = 0; mt < 2; mt++) {
                int r0 = wm * 32 + mt * 16 + q;
                af[mt][0] = As[r0][kb + r4];
                af[mt][1] = As[r0 + 8][kb + r4];
                af[mt][2] = As[r0][kb + r4 + 4];
                af[mt][3] = As[r0 + 8][kb + r4 + 4];
            }
#pragma unroll
            for (int nt = 0; nt < 4; nt++) {
                int c0 = wn * 32 + nt * 8 + q;
                bf[nt][0] = Bs[kb + r4][c0];
                bf[nt][1] = Bs[kb + r4 + 4][c0];
            }
#pragma unroll
            for (int mt = 0; mt < 2; mt++)
#pragma unroll
                for (int nt = 0; nt < 4; nt++) mma_tf32(acc[mt][nt], af[mt], bf[nt]);
        }
        __syncthreads();
    }

    int sA[2], dA[2], sB[2], dB[2];
#pragma unroll
    for (int mt = 0; mt < 2; mt++) {
        int gr0 = rowBase + wm * 32 + mt * 16 + q;
        sA[mt] = __ldg(gsrc + gr0); dA[mt] = __ldg(gdst + gr0);
        sB[mt] = __ldg(gsrc + gr0 + 8); dB[mt] = __ldg(gdst + gr0 + 8);
    }

    // ---- stage 2: c1 = relu(acc + P1[s] + P2[d] + c1b); c2 accumulate over 4 chunks ----
    float acc2[2][2][4];
#pragma unroll
    for (int mt = 0; mt < 2; mt++)
#pragma unroll
        for (int nt = 0; nt < 2; nt++)
#pragma unroll
            for (int j = 0; j < 4; j++) acc2[mt][nt][j] = 0.f;

    for (int kc = 0; kc < 4; kc++) {
        __syncthreads();
        if (wn == kc) {
#pragma unroll
            for (int mt = 0; mt < 2; mt++) {
                int r0 = wm * 32 + mt * 16 + q, r1 = r0 + 8;
#pragma unroll
                for (int nt = 0; nt < 4; nt++) {
                    int lc = nt * 8 + r4 * 2;
                    int gc = kc * 32 + lc;
                    float2 bv = *(const float2*)(c1b + gc);
                    float2 pa = *(const float2*)(p12 + (size_t)sA[mt] * 256 + gc);
                    float2 pb = *(const float2*)(p12 + (size_t)dA[mt] * 256 + 128 + gc);
                    As[r0][lc]     = f2tf(fmaxf(acc[mt][nt][0] + bv.x + pa.x + pb.x, 0.f));
                    As[r0][lc + 1] = f2tf(fmaxf(acc[mt][nt][1] + bv.y + pa.y + pb.y, 0.f));
                    float2 pc = *(const float2*)(p12 + (size_t)sB[mt] * 256 + gc);
                    float2 pd = *(const float2*)(p12 + (size_t)dB[mt] * 256 + 128 + gc);
                    As[r1][lc]     = f2tf(fmaxf(acc[mt][nt][2] + bv.x + pc.x + pd.x, 0.f));
                    As[r1][lc + 1] = f2tf(fmaxf(acc[mt][nt][3] + bv.y + pc.y + pd.y, 0.f));
                }
            }
        }
        {
            int kk = tid >> 4, cc = (tid & 15) * 4;
            float4 v = *(const float4*)(c2w + (size_t)(kc * 32 + kk) * 64 + cc);
            uint4 t;
            t.x = f2tf(v.x); t.y = f2tf(v.y); t.z = f2tf(v.z); t.w = f2tf(v.w);
            *(uint4*)&Bs[kk][cc] = t;
        }
        __syncthreads();
#pragma unroll
        for (int ks = 0; ks < 4; ks++) {
            int kb = ks * 8;
            unsigned af[2][4], bf[2][2];
#pragma unroll
            for (int mt = 0; mt < 2; mt++) {
                int r0 = wm * 32 + mt * 16 + q;
                af[mt][0] = As[r0][kb + r4];
                af[mt][1] = As[r0 + 8][kb + r4];
                af[mt][2] = As[r0][kb + r4 + 4];
                af[mt][3] = As[r0 + 8][kb + r4 + 4];
            }
#pragma unroll
            for (int nt = 0; nt < 2; nt++) {
                int c0 = wn * 16 + nt * 8 + q;
                bf[nt][0] = Bs[kb + r4][c0];
                bf[nt][1] = Bs[kb + r4 + 4][c0];
            }
#pragma unroll
            for (int mt = 0; mt < 2; mt++)
#pragma unroll
                for (int nt = 0; nt < 2; nt++) mma_tf32(acc2[mt][nt], af[mt], bf[nt]);
        }
    }

    // ---- stage 3: relu(c2 + c2b) . w3 + b3 ----
    float p0[2] = {0.f, 0.f}, p1[2] = {0.f, 0.f};
#pragma unroll
    for (int mt = 0; mt < 2; mt++) {
#pragma unroll
        for (int nt = 0; nt < 2; nt++) {
            int gc = wn * 16 + nt * 8 + r4 * 2;
            float2 bv = *(const float2*)(c2b + gc);
            float2 wv = *(const float2*)(w3 + gc);
            p0[mt] += fmaxf(acc2[mt][nt][0] + bv.x, 0.f) * wv.x +
                      fmaxf(acc2[mt][nt][1] + bv.y, 0.f) * wv.y;
            p1[mt] += fmaxf(acc2[mt][nt][2] + bv.x, 0.f) * wv.x +
                      fmaxf(acc2[mt][nt][3] + bv.y, 0.f) * wv.y;
        }
    }
    __syncthreads();
#pragma unroll
    for (int mt = 0; mt < 2; mt++) {
        float a = p0[mt], b = p1[mt];
        a += __shfl_xor_sync(0xffffffffu, a, 1); a += __shfl_xor_sync(0xffffffffu, a, 2);
        b += __shfl_xor_sync(0xffffffffu, b, 1); b += __shfl_xor_sync(0xffffffffu, b, 2);
        if (r4 == 0) {
            sp[wm * 32 + mt * 16 + q][wn] = a;
            sp[wm * 32 + mt * 16 + 8 + q][wn] = b;
        }
    }
    __syncthreads();
    if (tid < 128)
        out[rowBase + tid] = sp[tid][0] + sp[tid][1] + sp[tid][2] + sp[tid][3] + b3[0];
}

// ---------------- small kernels ----------------
__global__ void k_zero_all() {
    int i0 = blockIdx.x * blockDim.x + threadIdx.x;
    int stride = gridDim.x * blockDim.x;
    float4 z = make_float4(0.f, 0.f, 0.f, 0.f);
    for (int t = i0; t < NN * 32; t += stride) {
        ((float4*)g_xout)[t] = z;
        ((float4*)g_xin)[t] = z;
    }
    for (int t = i0; t < NN * 16; t += stride) ((float4*)g_lsum)[t] = z;
    for (int t = i0; t < NN; t += stride) { g_degs[t] = 0.f; g_degd[t] = 0.f; }
}

__global__ void k_build_xi(const float* __restrict__ node_stats) {
    int i0 = blockIdx.x * blockDim.x + threadIdx.x;
    int stride = gridDim.x * blockDim.x;
    for (int t = i0; t < NN * 32; t += stride) {
        int v = t >> 5, c4 = t & 31;
        float inv_s = 1.f / fmaxf(g_degs[v], 1.f);
        float inv_d = 1.f / fmaxf(g_degd[v], 1.f);
        float4 a = ((const float4*)(g_xout + (size_t)v * 128))[c4];
        a.x *= inv_s; a.y *= inv_s; a.z *= inv_s; a.w *= inv_s;
        *(float4*)(g_xi + (size_t)v * XI_LD + c4 * 4) = a;
        float4 b = ((const float4*)(g_xin + (size_t)v * 128))[c4];
        b.x *= inv_d; b.y *= inv_d; b.z *= inv_d; b.w *= inv_d;
        *(float4*)(g_xi + (size_t)v * XI_LD + 128 + c4 * 4) = b;
    }
    for (int t = i0; t < NN * 16; t += stride) {
        int v = t >> 4, c4 = t & 15;
        float inv_d = 1.f / fmaxf(g_degd[v], 1.f);
        float4 a = ((const float4*)(g_lsum + (size_t)v * 64))[c4];
        a.x *= inv_d; a.y *= inv_d; a.z *= inv_d; a.w *= inv_d;
        *(float4*)(g_la + (size_t)v * 64 + c4 * 4) = a;
    }
    for (int t = i0; t < NN * 2; t += stride) {
        int v = t >> 1, half = t & 1;
        float4 z = make_float4(0.f, 0.f, 0.f, 0.f);
        if (half == 0) { z.x = node_stats[v * 2]; z.y = node_stats[v * 2 + 1]; }
        *(float4*)(g_xi + (size_t)v * XI_LD + 256 + half * 4) = z;
    }
}

// ---------------- host ----------------
static float* sym(const void* s) { void* p = nullptr; cudaGetSymbolAddress(&p, s); return (float*)p; }

extern "C" void kernel_launch(void* const* d_in, const int* in_sizes, int n_in,
                              void* d_out, int out_size) {
    const float* node_stats = (const float*)d_in[1];
    const int*   edge_index = (const int*)d_in[2];
    const float* edge_attr  = (const float*)d_in[3];
    const float* epw = (const float*)d_in[4];
    const float* epb = (const float*)d_in[5];
    const float* g1wl = (const float*)d_in[6];
    const float* g1wr = (const float*)d_in[7];
    const float* g1we = (const float*)d_in[8];
    const float* g1att = (const float*)d_in[9];
    const float* g1b = (const float*)d_in[10];
    const float* n1g = (const float*)d_in[11];
    const float* n1b = (const float*)d_in[12];
    const float* g2wl = (const float*)d_in[13];
    const float* g2wr = (const float*)d_in[14];
    const float* g2we = (const float*)d_in[15];
    const float* g2att = (const float*)d_in[16];
    const float* g2b = (const float*)d_in[17];
    const float* n2g = (const float*)d_in[18];
    const float* n2b = (const float*)d_in[19];
    const float* c1w = (const float*)d_in[20];
    const float* c1b = (const float*)d_in[21];
    const float* c2w = (const float*)d_in[22];
    const float* c2b = (const float*)d_in[23];
    const float* c3w = (const float*)d_in[24];
    const float* c3b = (const float*)d_in[25];

    const int* src = edge_index;
    const int* dst = edge_index + EE;

    float* p_xi  = sym(g_xi);
    float* p_xlr = sym(g_xlr);
    float* p_la  = sym(g_la);
    float* p_h1  = sym(g_h1);
    float* p_h2  = sym(g_h2);

    const int T = 256;
    dim3 gNwarp((NN + 7) / 8);
    const int MB_E = EE / 128;                 // 3125
    const int MB_N = (NN + 127) / 128;         // 391
    const int NB_L = (E2 + 127) / 128;         // 3516
    const int NB_SCAN = (NN + 1023) / 1024;    // 49

    // ---- Stage A: zero, emb GEMM + scatter, xi, CSR build ----
    k_zero_all<<<1024, T>>>();
    gemm128<1, 1><<<dim3(1, MB_E), 512>>>(edge_attr, 64, 64, epw, nullptr, epb,
                                          nullptr, EE, 128, src, dst, edge_attr);
    k_build_xi<<<1024, T>>>(node_stats);
    csr_blocksum<<<NB_SCAN, 1024>>>();
    csr_scanblocks<<<1, 32>>>(NB_SCAN);
    csr_finalize<<<NB_SCAN, 1024>>>();
    csr_scatter<<<(E2 + T - 1) / T, T>>>(dst);

    // ---- GAT layer 1 (H=2): B = [g1wl|g1wr] split ----
    gemm128<0, 0><<<dim3(4, MB_N), 512>>>(p_xi, XI_LD, 258, g1wl, g1wr, nullptr,
                                          p_xlr, NN, 512, nullptr, nullptr, nullptr);
    k_gat_edge<2><<<NB_L, T>>>(edge_attr, p_la, g1we, g1att, p_xlr, src, dst);
    k_gat_gather<2><<<gNwarp, T>>>(p_xlr, src, g1b, n1g, n1b, p_h1);

    // ---- GAT layer 2 (H=1): B = [g2wl|g2wr] split ----
    gemm128<0, 0><<<dim3(2, MB_N), 512>>>(p_h1, 128, 128, g2wl, g2wr, nullptr,
                                          p_xlr, NN, 256, nullptr, nullptr, nullptr);
    k_gat_edge<1><<<NB_L, T>>>(edge_attr, p_la, g2we, g2att, p_xlr, src, dst);
    k_gat_gather<1><<<gNwarp, T>>>(p_xlr, src, g2b, n2g, n2b, p_h2);

    // ---- Classifier: P12 = h2 @ [c1w_src|c1w_dst] (split B), then fused edge kernel ----
    gemm128<0, 0><<<dim3(2, MB_N), 512>>>(p_h2, 128, 128, c1w, c1w + 128 * 128, nullptr,
                                          p_xlr, NN, 256, nullptr, nullptr, nullptr);
    k_cls_edge<<<MB_E, 512>>>(c1w, c1b, c2w, c2b, c3w, c3b,
                              src, dst, p_xlr, edge_attr, (float*)d_out);
}

// round 15
// speedup vs baseline: 1.0086x; 1.0086x over previous
#include <cuda_runtime.h>
#include <math.h>

#define NN 50000
#define EE 400000
#define E2 (EE + 50000)
#define XI_LD 264

// ---------------- scratch ----------------
__device__ float g_xi[NN * XI_LD + 64];
__device__ float g_xlr[NN * 512 + 64];   // xl|xr; reused as P12 for classifier
__device__ float g_la[NN * 64 + 64];
__device__ float g_xout[NN * 128];
__device__ float g_xin[NN * 128];
__device__ float g_lsum[NN * 64];
__device__ float g_degs[NN];
__device__ float g_degd[NN];
__device__ float g_h1[NN * 128 + 64];
__device__ float g_h2[NN * 128 + 64];
__device__ float g_logit[E2 * 2];
__device__ int   g_csr_off[NN + 1];
__device__ int   g_csr_pos[NN];
__device__ int   g_csr_edge[E2];
__device__ int   g_bsum[64];

// ---------------- helpers ----------------
__device__ __forceinline__ float lrelu02(float x) { return x > 0.f ? x : 0.2f * x; }

__device__ __forceinline__ float warp_sum(float v) {
#pragma unroll
    for (int o = 16; o; o >>= 1) v += __shfl_xor_sync(0xffffffffu, v, o);
    return v;
}
__device__ __forceinline__ int warp_sum_i(int v) {
#pragma unroll
    for (int o = 16; o; o >>= 1) v += __shfl_xor_sync(0xffffffffu, v, o);
    return v;
}

__device__ __forceinline__ void redv2(float* p, float a, float b) {
    asm volatile("red.global.add.v2.f32 [%0], {%1, %2};" :: "l"(p), "f"(a), "f"(b) : "memory");
}
__device__ __forceinline__ void redv4(float* p, float a, float b, float c, float d) {
    asm volatile("red.global.add.v4.f32 [%0], {%1, %2, %3, %4};"
                 :: "l"(p), "f"(a), "f"(b), "f"(c), "f"(d) : "memory");
}

__device__ __forceinline__ unsigned f2tf(float x) {
    unsigned u;
    asm("cvt.rna.tf32.f32 %0, %1;" : "=r"(u) : "f"(x));
    return u;
}

__device__ __forceinline__ void mma_tf32(float c[4], const unsigned a[4], const unsigned b[2]) {
    asm volatile(
        "mma.sync.aligned.m16n8k8.row.col.f32.tf32.tf32.f32 "
        "{%0,%1,%2,%3},{%4,%5,%6,%7},{%8,%9},{%0,%1,%2,%3};"
        : "+f"(c[0]), "+f"(c[1]), "+f"(c[2]), "+f"(c[3])
        : "r"(a[0]), "r"(a[1]), "r"(a[2]), "r"(a[3]), "r"(b[0]), "r"(b[1]));
}

// ======== wide TF32 GEMM: BM=128 BN=128 BK=32, 512 threads ========
// EPI: 0 = store C (+relu if ACT), 1 = emb scatter + ea sums
// B2: if non-null, B is column-concat [B | B2], each with row stride N/2.
template <int ACT, int EPI>
__global__ __launch_bounds__(512, 1)
void gemm128(const float* __restrict__ A, int lda, int K,
             const float* __restrict__ B, const float* __restrict__ B2,
             const float* __restrict__ bias,
             float* __restrict__ C, int M, int N,
             const int* __restrict__ gsrc, const int* __restrict__ gdst,
             const float* __restrict__ ea) {
    __shared__ unsigned As[128][36];
    __shared__ unsigned Bs[32][136];
    int tid = threadIdx.x;
    int warp = tid >> 5, lane = tid & 31;
    int wm = warp & 3, wn = warp >> 2;
    int rowBase = blockIdx.y * 128;
    int colBase = blockIdx.x * 128;
    int q = lane >> 2, r4 = lane & 3;

    float acc[2][4][4];
#pragma unroll
    for (int mt = 0; mt < 2; mt++)
#pragma unroll
        for (int nt = 0; nt < 4; nt++)
#pragma unroll
            for (int j = 0; j < 4; j++) acc[mt][nt][j] = 0.f;

    float4 pa[2], pb[2];
    auto loadA = [&](int k0) {
#pragma unroll
        for (int i = 0; i < 2; i++) {
            int idx = tid + i * 512;
            int row = idx >> 3, kk = (idx & 7) * 4;
            int gk = k0 + kk;
            float4 v = make_float4(0.f, 0.f, 0.f, 0.f);
            int gr = rowBase + row;
            if (gr < M && gk < lda) v = *(const float4*)(A + (size_t)gr * lda + gk);
            pa[i] = v;
        }
    };
    auto loadB = [&](int k0) {
#pragma unroll
        for (int i = 0; i < 2; i++) {
            int idx = tid + i * 512;
            int kk = idx >> 5, cc = (idx & 31) * 4;
            int gk = k0 + kk;
            float4 v = make_float4(0.f, 0.f, 0.f, 0.f);
            if (gk < K) {
                int gc = colBase + cc;
                if (B2) {
                    int N1 = N >> 1;
                    v = (gc < N1) ? *(const float4*)(B + (size_t)gk * N1 + gc)
                                  : *(const float4*)(B2 + (size_t)gk * N1 + gc - N1);
                } else {
                    v = *(const float4*)(B + (size_t)gk * N + gc);
                }
            }
            pb[i] = v;
        }
    };
    auto stsAB = [&]() {
#pragma unroll
        for (int i = 0; i < 2; i++) {
            int idx = tid + i * 512;
            int row = idx >> 3, kk = (idx & 7) * 4;
            uint4 t;
            t.x = f2tf(pa[i].x); t.y = f2tf(pa[i].y); t.z = f2tf(pa[i].z); t.w = f2tf(pa[i].w);
            *(uint4*)&As[row][kk] = t;
            int kb = idx >> 5, cc = (idx & 31) * 4;
            uint4 u;
            u.x = f2tf(pb[i].x); u.y = f2tf(pb[i].y); u.z = f2tf(pb[i].z); u.w = f2tf(pb[i].w);
            *(uint4*)&Bs[kb][cc] = u;
        }
    };

    loadA(0); loadB(0);
    for (int k0 = 0; k0 < K; k0 += 32) {
        stsAB();
        __syncthreads();
        if (k0 + 32 < K) { loadA(k0 + 32); loadB(k0 + 32); }
#pragma unroll
        for (int ks = 0; ks < 4; ks++) {
            int kb = ks * 8;
            unsigned af[2][4], bf[4][2];
#pragma unroll
            for (int mt = 0; mt < 2; mt++) {
                int r0 = wm * 32 + mt * 16 + q;
                af[mt][0] = As[r0][kb + r4];
                af[mt][1] = As[r0 + 8][kb + r4];
                af[mt][2] = As[r0][kb + r4 + 4];
                af[mt][3] = As[r0 + 8][kb + r4 + 4];
            }
#pragma unroll
            for (int nt = 0; nt < 4; nt++) {
                int c0 = wn * 32 + nt * 8 + q;
                bf[nt][0] = Bs[kb + r4][c0];
                bf[nt][1] = Bs[kb + r4 + 4][c0];
            }
#pragma unroll
            for (int mt = 0; mt < 2; mt++)
#pragma unroll
                for (int nt = 0; nt < 4; nt++) mma_tf32(acc[mt][nt], af[mt], bf[nt]);
        }
        __syncthreads();
    }

    if (EPI == 0) {
#pragma unroll
        for (int mt = 0; mt < 2; mt++) {
            int gr0 = rowBase + wm * 32 + mt * 16 + q;
            int gr1 = gr0 + 8;
#pragma unroll
            for (int nt = 0; nt < 4; nt++) {
                int gc = colBase + wn * 32 + nt * 8 + r4 * 2;
                float2 bv = make_float2(0.f, 0.f);
                if (bias) bv = *(const float2*)(bias + gc);
                float o0 = acc[mt][nt][0] + bv.x, o1 = acc[mt][nt][1] + bv.y;
                float o2 = acc[mt][nt][2] + bv.x, o3 = acc[mt][nt][3] + bv.y;
                if (ACT == 1) {
                    o0 = fmaxf(o0, 0.f); o1 = fmaxf(o1, 0.f);
                    o2 = fmaxf(o2, 0.f); o3 = fmaxf(o3, 0.f);
                }
                if (gr0 < M) *(float2*)(C + (size_t)gr0 * N + gc) = make_float2(o0, o1);
                if (gr1 < M) *(float2*)(C + (size_t)gr1 * N + gc) = make_float2(o2, o3);
            }
        }
    } else {
        // emb scatter: relu(acc+bias) -> xout[src], xin[dst]
#pragma unroll
        for (int mt = 0; mt < 2; mt++) {
            int gr0 = rowBase + wm * 32 + mt * 16 + q;
            int gr1 = gr0 + 8;
            int s0 = __ldg(gsrc + gr0), d0 = __ldg(gdst + gr0);
            int s1 = __ldg(gsrc + gr1), d1 = __ldg(gdst + gr1);
#pragma unroll
            for (int nt = 0; nt < 4; nt++) {
                int gc = wn * 32 + nt * 8 + r4 * 2;
                float2 bv = *(const float2*)(bias + gc);
                float v0 = fmaxf(acc[mt][nt][0] + bv.x, 0.f);
                float v1 = fmaxf(acc[mt][nt][1] + bv.y, 0.f);
                float v2 = fmaxf(acc[mt][nt][2] + bv.x, 0.f);
                float v3 = fmaxf(acc[mt][nt][3] + bv.y, 0.f);
                redv2(&g_xout[(size_t)s0 * 128 + gc], v0, v1);
                redv2(&g_xin[(size_t)d0 * 128 + gc], v0, v1);
                redv2(&g_xout[(size_t)s1 * 128 + gc], v2, v3);
                redv2(&g_xin[(size_t)d1 * 128 + gc], v2, v3);
            }
        }
        int row = tid >> 2, part = tid & 3;
        int e = rowBase + row;
        int s = __ldg(gsrc + e), d = __ldg(gdst + e);
        const float4* pea = (const float4*)(ea + (size_t)e * 64) + part * 4;
#pragma unroll
        for (int j = 0; j < 4; j++) {
            float4 v = pea[j];
            redv4(&g_lsum[(size_t)d * 64 + part * 16 + j * 4], v.x, v.y, v.z, v.w);
        }
        if (part == 0) { atomicAdd(&g_degs[s], 1.f); atomicAdd(&g_degd[d], 1.f); }
    }
}

// ======== CSR build ========
__global__ void csr_blocksum() {
    int v = blockIdx.x * 1024 + threadIdx.x;
    int c = (v < NN) ? (int)(g_degd[v] + 0.5f) + 1 : 0;
    __shared__ int ws[32];
    int wsum = warp_sum_i(c);
    if ((threadIdx.x & 31) == 0) ws[threadIdx.x >> 5] = wsum;
    __syncthreads();
    if (threadIdx.x < 32) {
        int t = ws[threadIdx.x];
        t = warp_sum_i(t);
        if (threadIdx.x == 0) g_bsum[blockIdx.x] = t;
    }
}
__global__ void csr_scanblocks(int nb) {
    if (threadIdx.x == 0) {
        int run = 0;
        for (int b = 0; b < nb; b++) { int t = g_bsum[b]; g_bsum[b] = run; run += t; }
    }
}
__global__ void csr_finalize() {
    __shared__ int sm[1024];
    int tid = threadIdx.x;
    int v = blockIdx.x * 1024 + tid;
    int c = (v < NN) ? (int)(g_degd[v] + 0.5f) + 1 : 0;
    sm[tid] = c;
    __syncthreads();
    for (int o = 1; o < 1024; o <<= 1) {
        int t = (tid >= o) ? sm[tid - o] : 0;
        __syncthreads();
        sm[tid] += t;
        __syncthreads();
    }
    int incl = sm[tid];
    int base = g_bsum[blockIdx.x];
    if (v < NN) {
        int off = base + incl - c;
        g_csr_off[v] = off;
        g_csr_pos[v] = off;
        if (v == NN - 1) g_csr_off[NN] = base + incl;
    }
}
__global__ void csr_scatter(const int* __restrict__ dst) {
    int i = blockIdx.x * blockDim.x + threadIdx.x;
    if (i < EE) {
        int d = dst[i];
        int pos = atomicAdd(&g_csr_pos[d], 1);
        g_csr_edge[pos] = i;
    } else if (i < E2) {
        int v = i - EE;
        g_csr_edge[g_csr_off[v + 1] - 1] = i;   // self-loop last in segment
    }
}

// ======== ew GEMM + GATv2 logit (CSR edge order, logits only) ========
template <int H>
__global__ void k_gat_edge(const float* __restrict__ ea, const float* __restrict__ la,
                           const float* __restrict__ we, const float* __restrict__ att,
                           const float* __restrict__ xlr,
                           const int* __restrict__ src, const int* __restrict__ dst) {
    const int W = 2 * H * 128;
    const int XOFF = H * 128;
    const int NB = H * 128;
    __shared__ unsigned As[128][68];
    __shared__ unsigned Bs[32][72];
    __shared__ float sp[128][2];
    __shared__ float lg[H][128];
    int tid = threadIdx.x;
    int warp = tid >> 5, lane = tid & 31;
    int wm = warp & 3, wn = warp >> 2;
    int q = lane >> 2, r4 = lane & 3;
    int e0 = blockIdx.x * 128;

    for (int i = tid; i < H * 128; i += 256) lg[i >> 7][i & 127] = 0.f;

#pragma unroll
    for (int i = 0; i < 8; i++) {
        int idx = tid + i * 256;
        int row = idx >> 4, gc = (idx & 15) * 4;
        int p = e0 + row;
        float4 v = make_float4(0.f, 0.f, 0.f, 0.f);
        if (p < E2) {
            int e = __ldg(g_csr_edge + p);
            if (e < EE) v = *(const float4*)(ea + (size_t)e * 64 + gc);
            else        v = *(const float4*)(la + (size_t)(e - EE) * 64 + gc);
        }
        uint4 t;
        t.x = f2tf(v.x); t.y = f2tf(v.y); t.z = f2tf(v.z); t.w = f2tf(v.w);
        *(uint4*)&As[row][gc] = t;
    }
    int ss[2][2], dd[2][2];
    bool vld[2][2];
#pragma unroll
    for (int mt = 0; mt < 2; mt++)
#pragma unroll
        for (int hf = 0; hf < 2; hf++) {
            int p = e0 + wm * 32 + mt * 16 + hf * 8 + q;
            bool v = p < E2;
            vld[mt][hf] = v;
            if (!v) { ss[mt][hf] = 0; dd[mt][hf] = 0; }
            else {
                int e = __ldg(g_csr_edge + p);
                if (e < EE) { ss[mt][hf] = __ldg(src + e); dd[mt][hf] = __ldg(dst + e); }
                else { ss[mt][hf] = e - EE; dd[mt][hf] = e - EE; }
            }
        }
    __syncthreads();

    for (int strip = 0; strip < 2 * H; strip++) {
        float acc[2][4][4];
#pragma unroll
        for (int mt = 0; mt < 2; mt++)
#pragma unroll
            for (int nt = 0; nt < 4; nt++)
#pragma unroll
                for (int j = 0; j < 4; j++) acc[mt][nt][j] = 0.f;

        for (int kt = 0; kt < 2; kt++) {
            __syncthreads();
#pragma unroll
            for (int i = 0; i < 2; i++) {
                int idx = tid + i * 256;
                int kk = idx >> 4, cc = (idx & 15) * 4;
                float4 v = *(const float4*)(we + (size_t)(kt * 32 + kk) * NB + strip * 64 + cc);
                uint4 t;
                t.x = f2tf(v.x); t.y = f2tf(v.y); t.z = f2tf(v.z); t.w = f2tf(v.w);
                *(uint4*)&Bs[kk][cc] = t;
            }
            __syncthreads();
#pragma unroll
            for (int ks = 0; ks < 4; ks++) {
                int kb = ks * 8;
                unsigned af[2][4], bf[4][2];
#pragma unroll
                for (int mt = 0; mt < 2; mt++) {
                    int r0 = wm * 32 + mt * 16 + q;
                    int ka = kt * 32 + kb;
                    af[mt][0] = As[r0][ka + r4];
                    af[mt][1] = As[r0 + 8][ka + r4];
                    af[mt][2] = As[r0][ka + r4 + 4];
                    af[mt][3] = As[r0 + 8][ka + r4 + 4];
                }
#pragma unroll
                for (int nt = 0; nt < 4; nt++) {
                    int c0 = wn * 32 + nt * 8 + q;
                    bf[nt][0] = Bs[kb + r4][c0];
                    bf[nt][1] = Bs[kb + r4 + 4][c0];
                }
#pragma unroll
                for (int mt = 0; mt < 2; mt++)
#pragma unroll
                    for (int nt = 0; nt < 4; nt++) mma_tf32(acc[mt][nt], af[mt], bf[nt]);
            }
        }

        int h = strip >> 1;
        float prow[2][2] = {{0.f, 0.f}, {0.f, 0.f}};
#pragma unroll
        for (int mt = 0; mt < 2; mt++) {
#pragma unroll
            for (int nt = 0; nt < 4; nt++) {
                int gc = strip * 64 + wn * 32 + nt * 8 + r4 * 2;
                int ch = gc & 127;
                float2 at = *(const float2*)(att + h * 128 + ch);
                if (vld[mt][0]) {
                    float2 xv = *(const float2*)(xlr + (size_t)ss[mt][0] * W + h * 128 + ch);
                    float2 rv = *(const float2*)(xlr + (size_t)dd[mt][0] * W + XOFF + h * 128 + ch);
                    prow[mt][0] += lrelu02(acc[mt][nt][0] + xv.x + rv.x) * at.x +
                                   lrelu02(acc[mt][nt][1] + xv.y + rv.y) * at.y;
                }
                if (vld[mt][1]) {
                    float2 xv = *(const float2*)(xlr + (size_t)ss[mt][1] * W + h * 128 + ch);
                    float2 rv = *(const float2*)(xlr + (size_t)dd[mt][1] * W + XOFF + h * 128 + ch);
                    prow[mt][1] += lrelu02(acc[mt][nt][2] + xv.x + rv.x) * at.x +
                                   lrelu02(acc[mt][nt][3] + xv.y + rv.y) * at.y;
                }
            }
        }
#pragma unroll
        for (int mt = 0; mt < 2; mt++)
#pragma unroll
            for (int hf = 0; hf < 2; hf++) {
                float p = prow[mt][hf];
                p += __shfl_xor_sync(0xffffffffu, p, 1);
                p += __shfl_xor_sync(0xffffffffu, p, 2);
                if (r4 == 0) sp[wm * 32 + mt * 16 + hf * 8 + q][wn] = p;
            }
        __syncthreads();
        if (tid < 128) lg[h][tid] += sp[tid][0] + sp[tid][1];
    }
    __syncthreads();
    if (tid < 128) {
        int p = e0 + tid;
        if (p < E2) {
#pragma unroll
            for (int h = 0; h < H; h++) g_logit[(size_t)p * H + h] = lg[h][tid];
        }
    }
}

// ======== warp-per-node: softmax-aggregate + heads mean + LN + ELU ========
template <int H>
__global__ void k_gat_gather(const float* __restrict__ xlr, const int* __restrict__ src,
                             const float* __restrict__ bias, const float* __restrict__ gam,
                             const float* __restrict__ bet, float* __restrict__ out) {
    const int W = 2 * H * 128;
    int v = (blockIdx.x * blockDim.x + threadIdx.x) >> 5;
    int lane = threadIdx.x & 31;
    if (v >= NN) return;
    int beg = g_csr_off[v], end = g_csr_off[v + 1];
    float acc[H][4];
    float den[H];
#pragma unroll
    for (int h = 0; h < H; h++) {
        den[h] = 0.f;
#pragma unroll
        for (int j = 0; j < 4; j++) acc[h][j] = 0.f;
    }
    for (int p = beg; p < end; p++) {
        int e = __ldg(g_csr_edge + p);
        int s = (e < EE) ? __ldg(src + e) : v;
#pragma unroll
        for (int h = 0; h < H; h++) {
            float a = expf(__ldg(g_logit + (size_t)p * H + h));
            den[h] += a;
            float4 x = ((const float4*)(xlr + (size_t)s * W + h * 128))[lane];
            acc[h][0] += a * x.x; acc[h][1] += a * x.y;
            acc[h][2] += a * x.z; acc[h][3] += a * x.w;
        }
    }
    float vals[4];
    int c0 = lane * 4;
    if (H == 2) {
        float i0 = 1.f / fmaxf(den[0], 1e-16f);
        float i1 = 1.f / fmaxf(den[1], 1e-16f);
#pragma unroll
        for (int j = 0; j < 4; j++)
            vals[j] = 0.5f * (acc[0][j] * i0 + acc[H - 1][j] * i1) + bias[c0 + j];
    } else {
        float i0 = 1.f / fmaxf(den[0], 1e-16f);
#pragma unroll
        for (int j = 0; j < 4; j++) vals[j] = acc[0][j] * i0 + bias[c0 + j];
    }
    float mu = warp_sum(vals[0] + vals[1] + vals[2] + vals[3]) * (1.f / 128.f);
    float sq = 0.f;
#pragma unroll
    for (int j = 0; j < 4; j++) { float dlt = vals[j] - mu; sq += dlt * dlt; }
    float var = warp_sum(sq) * (1.f / 128.f);
    float rstd = rsqrtf(var + 1e-5f);
#pragma unroll
    for (int j = 0; j < 4; j++) {
        int c = c0 + j;
        float y = (vals[j] - mu) * rstd * gam[c] + bet[c];
        out[(size_t)v * 128 + c] = y > 0.f ? y : (expf(y) - 1.f);
    }
}

// ======== classifier edge kernel: ea@c1w_e + P1[s]+P2[d] -> relu -> c2 -> c3 ========
__global__ __launch_bounds__(512, 1)
void k_cls_edge(const float* __restrict__ c1w, const float* __restrict__ c1b,
                const float* __restrict__ c2w, const float* __restrict__ c2b,
                const float* __restrict__ w3, const float* __restrict__ b3,
                const int* __restrict__ gsrc, const int* __restrict__ gdst,
                const float* __restrict__ p12, const float* __restrict__ ea,
                float* __restrict__ out) {
    __shared__ unsigned As[128][36];
    __shared__ unsigned Bs[32][136];
    __shared__ float sp[128][4];
    int tid = threadIdx.x;
    int warp = tid >> 5, lane = tid & 31;
    int wm = warp & 3, wn = warp >> 2;
    int rowBase = blockIdx.x * 128;
    int q = lane >> 2, r4 = lane & 3;

    // ---- stage 1: ea(128x64) @ c1w[256:320] (64x128), register double-buffered ----
    float acc[2][4][4];
#pragma unroll
    for (int mt = 0; mt < 2; mt++)
#pragma unroll
        for (int nt = 0; nt < 4; nt++)
#pragma unroll
            for (int j = 0; j < 4; j++) acc[mt][nt][j] = 0.f;

    float4 pa[2], pb[2];
    auto loadAB = [&](int k0) {
#pragma unroll
        for (int i = 0; i < 2; i++) {
            int idx = tid + i * 512;
            int row = idx >> 3, kk = (idx & 7) * 4;
            pa[i] = *(const float4*)(ea + (size_t)(rowBase + row) * 64 + k0 + kk);
            int kb = idx >> 5, cc = (idx & 31) * 4;
            pb[i] = *(const float4*)(c1w + (size_t)(256 + k0 + kb) * 128 + cc);
        }
    };
    auto stsAB = [&]() {
#pragma unroll
        for (int i = 0; i < 2; i++) {
            int idx = tid + i * 512;
            int row = idx >> 3, kk = (idx & 7) * 4;
            uint4 t;
            t.x = f2tf(pa[i].x); t.y = f2tf(pa[i].y); t.z = f2tf(pa[i].z); t.w = f2tf(pa[i].w);
            *(uint4*)&As[row][kk] = t;
            int kb = idx >> 5, cc = (idx & 31) * 4;
            uint4 u;
            u.x = f2tf(pb[i].x); u.y = f2tf(pb[i].y); u.z = f2tf(pb[i].z); u.w = f2tf(pb[i].w);
            *(uint4*)&Bs[kb][cc] = u;
        }
    };

    loadAB(0);
    for (int k0 = 0; k0 < 64; k0 += 32) {
        stsAB();
        __syncthreads();
        if (k0 + 32 < 64) loadAB(k0 + 32);
#pragma unroll
        for (int ks = 0; ks < 4; ks++) {
            int kb = ks * 8;
            unsigned af[2][4], bf[4][2];
#pragma unroll
            for (int mt = 0; mt < 2; mt++) {
                int r0 = wm * 32 + mt * 16 + q;
                af[mt][0] = As[r0][kb + r4];
                af[mt][1] = As[r0 + 8][kb + r4];
                af[mt][2] = As[r0][kb + r4 + 4];
                af[mt][3] = As[r0 + 8][kb + r4 + 4];
            }
#pragma unroll
            for (int nt = 0; nt < 4; nt++) {
                int c0 = wn * 32 + nt * 8 + q;
                bf[nt][0] = Bs[kb + r4][c0];
                bf[nt][1] = Bs[kb + r4 + 4][c0];
            }
#pragma unroll
            for (int mt = 0; mt < 2; mt++)
#pragma unroll
                for (int nt = 0; nt < 4; nt++) mma_tf32(acc[mt][nt], af[mt], bf[nt]);
        }
        __syncthreads();
    }

    int sA[2], dA[2], sB[2], dB[2];
#pragma unroll
    for (int mt = 0; mt < 2; mt++) {
        int gr0 = rowBase + wm * 32 + mt * 16 + q;
        sA[mt] = __ldg(gsrc + gr0); dA[mt] = __ldg(gdst + gr0);
        sB[mt] = __ldg(gsrc + gr0 + 8); dB[mt] = __ldg(gdst + gr0 + 8);
    }

    // ---- stage 2: c1 = relu(acc + P1[s] + P2[d] + c1b); c2 accumulate over 4 chunks ----
    float acc2[2][2][4];
#pragma unroll
    for (int mt = 0; mt < 2; mt++)
#pragma unroll
        for (int nt = 0; nt < 2; nt++)
#pragma unroll
            for (int j = 0; j < 4; j++) acc2[mt][nt][j] = 0.f;

    for (int kc = 0; kc < 4; kc++) {
        __syncthreads();
        if (wn == kc) {
#pragma unroll
            for (int mt = 0; mt < 2; mt++) {
                int r0 = wm * 32 + mt * 16 + q, r1 = r0 + 8;
#pragma unroll
                for (int nt = 0; nt < 4; nt++) {
                    int lc = nt * 8 + r4 * 2;
                    int gc = kc * 32 + lc;
                    float2 bv = *(const float2*)(c1b + gc);
                    float2 pa2 = *(const float2*)(p12 + (size_t)sA[mt] * 256 + gc);
                    float2 pb2 = *(const float2*)(p12 + (size_t)dA[mt] * 256 + 128 + gc);
                    As[r0][lc]     = f2tf(fmaxf(acc[mt][nt][0] + bv.x + pa2.x + pb2.x, 0.f));
                    As[r0][lc + 1] = f2tf(fmaxf(acc[mt][nt][1] + bv.y + pa2.y + pb2.y, 0.f));
                    float2 pc = *(const float2*)(p12 + (size_t)sB[mt] * 256 + gc);
                    float2 pd = *(const float2*)(p12 + (size_t)dB[mt] * 256 + 128 + gc);
                    As[r1][lc]     = f2tf(fmaxf(acc[mt][nt][2] + bv.x + pc.x + pd.x, 0.f));
                    As[r1][lc + 1] = f2tf(fmaxf(acc[mt][nt][3] + bv.y + pc.y + pd.y, 0.f));
                }
            }
        }
        {
            int kk = tid >> 4, cc = (tid & 15) * 4;
            float4 v = *(const float4*)(c2w + (size_t)(kc * 32 + kk) * 64 + cc);
            uint4 t;
            t.x = f2tf(v.x); t.y = f2tf(v.y); t.z = f2tf(v.z); t.w = f2tf(v.w);
            *(uint4*)&Bs[kk][cc] = t;
        }
        __syncthreads();
#pragma unroll
        for (int ks = 0; ks < 4; ks++) {
            int kb = ks * 8;
            unsigned af[2][4], bf[2][2];
#pragma unroll
            for (int mt = 0; mt < 2; mt++) {
                int r0 = wm * 32 + mt * 16 + q;
                af[mt][0] = As[r0][kb + r4];
                af[mt][1] = As[r0 + 8][kb + r4];
                af[mt][2] = As[r0][kb + r4 + 4];
                af[mt][3] = As[r0 + 8][kb + r4 + 4];
            }
#pragma unroll
            for (int nt = 0; nt < 2; nt++) {
                int c0 = wn * 16 + nt * 8 + q;
                bf[nt][0] = Bs[kb + r4][c0];
                bf[nt][1] = Bs[kb + r4 + 4][c0];
            }
#pragma unroll
            for (int mt = 0; mt < 2; mt++)
#pragma unroll
                for (int nt = 0; nt < 2; nt++) mma_tf32(acc2[mt][nt], af[mt], bf[nt]);
        }
    }

    // ---- stage 3: relu(c2 + c2b) . w3 + b3 ----
    float p0[2] = {0.f, 0.f}, p1[2] = {0.f, 0.f};
#pragma unroll
    for (int mt = 0; mt < 2; mt++) {
#pragma unroll
        for (int nt = 0; nt < 2; nt++) {
            int gc = wn * 16 + nt * 8 + r4 * 2;
            float2 bv = *(const float2*)(c2b + gc);
            float2 wv = *(const float2*)(w3 + gc);
            p0[mt] += fmaxf(acc2[mt][nt][0] + bv.x, 0.f) * wv.x +
                      fmaxf(acc2[mt][nt][1] + bv.y, 0.f) * wv.y;
            p1[mt] += fmaxf(acc2[mt][nt][2] + bv.x, 0.f) * wv.x +
                      fmaxf(acc2[mt][nt][3] + bv.y, 0.f) * wv.y;
        }
    }
    __syncthreads();
#pragma unroll
    for (int mt = 0; mt < 2; mt++) {
        float a = p0[mt], b = p1[mt];
        a += __shfl_xor_sync(0xffffffffu, a, 1); a += __shfl_xor_sync(0xffffffffu, a, 2);
        b += __shfl_xor_sync(0xffffffffu, b, 1); b += __shfl_xor_sync(0xffffffffu, b, 2);
        if (r4 == 0) {
            sp[wm * 32 + mt * 16 + q][wn] = a;
            sp[wm * 32 + mt * 16 + 8 + q][wn] = b;
        }
    }
    __syncthreads();
    if (tid < 128)
        out[rowBase + tid] = sp[tid][0] + sp[tid][1] + sp[tid][2] + sp[tid][3] + b3[0];
}

// ---------------- small kernels ----------------
__global__ void k_zero_all() {
    int i0 = blockIdx.x * blockDim.x + threadIdx.x;
    int stride = gridDim.x * blockDim.x;
    float4 z = make_float4(0.f, 0.f, 0.f, 0.f);
    for (int t = i0; t < NN * 32; t += stride) {
        ((float4*)g_xout)[t] = z;
        ((float4*)g_xin)[t] = z;
    }
    for (int t = i0; t < NN * 16; t += stride) ((float4*)g_lsum)[t] = z;
    for (int t = i0; t < NN; t += stride) { g_degs[t] = 0.f; g_degd[t] = 0.f; }
}

__global__ void k_build_xi(const float* __restrict__ node_stats) {
    int i0 = blockIdx.x * blockDim.x + threadIdx.x;
    int stride = gridDim.x * blockDim.x;
    for (int t = i0; t < NN * 32; t += stride) {
        int v = t >> 5, c4 = t & 31;
        float inv_s = 1.f / fmaxf(g_degs[v], 1.f);
        float inv_d = 1.f / fmaxf(g_degd[v], 1.f);
        float4 a = ((const float4*)(g_xout + (size_t)v * 128))[c4];
        a.x *= inv_s; a.y *= inv_s; a.z *= inv_s; a.w *= inv_s;
        *(float4*)(g_xi + (size_t)v * XI_LD + c4 * 4) = a;
        float4 b = ((const float4*)(g_xin + (size_t)v * 128))[c4];
        b.x *= inv_d; b.y *= inv_d; b.z *= inv_d; b.w *= inv_d;
        *(float4*)(g_xi + (size_t)v * XI_LD + 128 + c4 * 4) = b;
    }
    for (int t = i0; t < NN * 16; t += stride) {
        int v = t >> 4, c4 = t & 15;
        float inv_d = 1.f / fmaxf(g_degd[v], 1.f);
        float4 a = ((const float4*)(g_lsum + (size_t)v * 64))[c4];
        a.x *= inv_d; a.y *= inv_d; a.z *= inv_d; a.w *= inv_d;
        *(float4*)(g_la + (size_t)v * 64 + c4 * 4) = a;
    }
    for (int t = i0; t < NN * 2; t += stride) {
        int v = t >> 1, half = t & 1;
        float4 z = make_float4(0.f, 0.f, 0.f, 0.f);
        if (half == 0) { z.x = node_stats[v * 2]; z.y = node_stats[v * 2 + 1]; }
        *(float4*)(g_xi + (size_t)v * XI_LD + 256 + half * 4) = z;
    }
}

// ---------------- host ----------------
static float* sym(const void* s) { void* p = nullptr; cudaGetSymbolAddress(&p, s); return (float*)p; }

extern "C" void kernel_launch(void* const* d_in, const int* in_sizes, int n_in,
                              void* d_out, int out_size) {
    const float* node_stats = (const float*)d_in[1];
    const int*   edge_index = (const int*)d_in[2];
    const float* edge_attr  = (const float*)d_in[3];
    const float* epw = (const float*)d_in[4];
    const float* epb = (const float*)d_in[5];
    const float* g1wl = (const float*)d_in[6];
    const float* g1wr = (const float*)d_in[7];
    const float* g1we = (const float*)d_in[8];
    const float* g1att = (const float*)d_in[9];
    const float* g1b = (const float*)d_in[10];
    const float* n1g = (const float*)d_in[11];
    const float* n1b = (const float*)d_in[12];
    const float* g2wl = (const float*)d_in[13];
    const float* g2wr = (const float*)d_in[14];
    const float* g2we = (const float*)d_in[15];
    const float* g2att = (const float*)d_in[16];
    const float* g2b = (const float*)d_in[17];
    const float* n2g = (const float*)d_in[18];
    const float* n2b = (const float*)d_in[19];
    const float* c1w = (const float*)d_in[20];
    const float* c1b = (const float*)d_in[21];
    const float* c2w = (const float*)d_in[22];
    const float* c2b = (const float*)d_in[23];
    const float* c3w = (const float*)d_in[24];
    const float* c3b = (const float*)d_in[25];

    const int* src = edge_index;
    const int* dst = edge_index + EE;

    float* p_xi  = sym(g_xi);
    float* p_xlr = sym(g_xlr);
    float* p_la  = sym(g_la);
    float* p_h1  = sym(g_h1);
    float* p_h2  = sym(g_h2);

    const int T = 256;
    dim3 gNwarp((NN + 7) / 8);
    const int MB_E = EE / 128;                 // 3125
    const int MB_N = (NN + 127) / 128;         // 391
    const int NB_L = (E2 + 127) / 128;         // 3516
    const int NB_SCAN = (NN + 1023) / 1024;    // 49

    // ---- Stage A: zero, emb GEMM + scatter, xi, CSR build ----
    k_zero_all<<<1024, T>>>();
    gemm128<1, 1><<<dim3(1, MB_E), 512>>>(edge_attr, 64, 64, epw, nullptr, epb,
                                          nullptr, EE, 128, src, dst, edge_attr);
    k_build_xi<<<1024, T>>>(node_stats);
    csr_blocksum<<<NB_SCAN, 1024>>>();
    csr_scanblocks<<<1, 32>>>(NB_SCAN);
    csr_finalize<<<NB_SCAN, 1024>>>();
    csr_scatter<<<(E2 + T - 1) / T, T>>>(dst);

    // ---- GAT layer 1 (H=2): B = [g1wl|g1wr] split ----
    gemm128<0, 0><<<dim3(4, MB_N), 512>>>(p_xi, XI_LD, 258, g1wl, g1wr, nullptr,
                                          p_xlr, NN, 512, nullptr, nullptr, nullptr);
    k_gat_edge<2><<<NB_L, T>>>(edge_attr, p_la, g1we, g1att, p_xlr, src, dst);
    k_gat_gather<2><<<gNwarp, T>>>(p_xlr, src, g1b, n1g, n1b, p_h1);

    // ---- GAT layer 2 (H=1): B = [g2wl|g2wr] split ----
    gemm128<0, 0><<<dim3(2, MB_N), 512>>>(p_h1, 128, 128, g2wl, g2wr, nullptr,
                                          p_xlr, NN, 256, nullptr, nullptr, nullptr);
    k_gat_edge<1><<<NB_L, T>>>(edge_attr, p_la, g2we, g2att, p_xlr, src, dst);
    k_gat_gather<1><<<gNwarp, T>>>(p_xlr, src, g2b, n2g, n2b, p_h2);

    // ---- Classifier: P12 = h2 @ [c1w_src|c1w_dst] (split B), then fused edge kernel ----
    gemm128<0, 0><<<dim3(2, MB_N), 512>>>(p_h2, 128, 128, c1w, c1w + 128 * 128, nullptr,
                                          p_xlr, NN, 256, nullptr, nullptr, nullptr);
    k_cls_edge<<<MB_E, 512>>>(c1w, c1b, c2w, c2b, c3w, c3b,
                              src, dst, p_xlr, edge_attr, (float*)d_out);
}